// round 14
// baseline (speedup 1.0000x reference)
#include <cuda_runtime.h>
#include <cuda_fp16.h>
#include <cstdint>

#define DIM     128
#define NMAX    100000
#define MAXDEG  128
#define TILE_M  128
#define YPAD    136         // Ysm row stride in halfs (272B: LDSM conflict-free)
#define WPAD    40          // Wsm row stride in halfs (80B per 32-col phase)

// ---------------------------------------------------------------------------
// Scratch (allocation-free rule: module-scope device arrays)
// ---------------------------------------------------------------------------
__device__ int    g_deg[NMAX];
__device__ int    g_bucket[(size_t)NMAX * MAXDEG];     // 51.2 MB
__device__ __half g_xh[(size_t)NMAX * DIM];            // 25.6 MB  x in fp16
__device__ __half g_Wh[DIM * DIM];                     // W in fp16

__device__ __forceinline__ uint32_t smem_u32(const void* p) {
    uint32_t a;
    asm("{ .reg .u64 t; cvta.to.shared.u64 t, %1; cvt.u32.u64 %0, t; }"
        : "=r"(a) : "l"(p));
    return a;
}

__device__ __forceinline__ uint4 cvt8_f32_to_h16(float4 v0, float4 v1) {
    uint4 o;
    __half2 h;
    h = __float22half2_rn(make_float2(v0.x, v0.y)); o.x = *(const uint32_t*)&h;
    h = __float22half2_rn(make_float2(v0.z, v0.w)); o.y = *(const uint32_t*)&h;
    h = __float22half2_rn(make_float2(v1.x, v1.y)); o.z = *(const uint32_t*)&h;
    h = __float22half2_rn(make_float2(v1.z, v1.w)); o.w = *(const uint32_t*)&h;
    return o;
}

// ---------------------------------------------------------------------------
// K0: init — zero degrees + x->fp16 + W->fp16 (8 floats/thread, proven)
// ---------------------------------------------------------------------------
__global__ void init_kernel(const float* __restrict__ x,
                            const float* __restrict__ W, int n) {
    int i = blockIdx.x * blockDim.x + threadIdx.x;       // one per 8 floats
    size_t total8 = (size_t)n * (DIM / 8);               // 1.6M
    if ((size_t)i < total8) {
        const float4* p = (const float4*)x + (size_t)i * 2;
        ((uint4*)g_xh)[i] = cvt8_f32_to_h16(p[0], p[1]);
    }
    if (i < n) g_deg[i] = 0;
    if (i < DIM * DIM / 8) {
        const float4* p = (const float4*)W + (size_t)i * 2;
        ((uint4*)g_Wh)[i] = cvt8_f32_to_h16(p[0], p[1]);
    }
}

// ---------------------------------------------------------------------------
// K1: count degrees + scatter neighbor lists (edge_index delivered as int32)
// ---------------------------------------------------------------------------
__global__ void fill_kernel(const int* __restrict__ ei, int e, int n) {
    int i = blockIdx.x * blockDim.x + threadIdx.x;
    if (i >= e) return;
    int row = ei[i];
    int col = ei[(size_t)e + i];
    if ((unsigned)row >= (unsigned)n) return;
    if ((unsigned)col >= (unsigned)n) return;
    int slot = atomicAdd(&g_deg[row], 1);
    if (slot < MAXDEG) g_bucket[(size_t)row * MAXDEG + slot] = col;
}

// ---------------------------------------------------------------------------
// mma.sync m16n8k16 fp16 -> fp32
// ---------------------------------------------------------------------------
__device__ __forceinline__ void mma16816(float c[4],
                                         uint32_t a0, uint32_t a1,
                                         uint32_t a2, uint32_t a3,
                                         uint32_t b0, uint32_t b1) {
    asm volatile(
        "mma.sync.aligned.m16n8k16.row.col.f32.f16.f16.f32 "
        "{%0,%1,%2,%3}, {%4,%5,%6,%7}, {%8,%9}, {%0,%1,%2,%3};"
        : "+f"(c[0]), "+f"(c[1]), "+f"(c[2]), "+f"(c[3])
        : "r"(a0), "r"(a1), "r"(a2), "r"(a3), "r"(b0), "r"(b1));
}

__device__ __forceinline__ void ldsm_x4(uint32_t r[4], uint32_t addr) {
    asm volatile(
        "ldmatrix.sync.aligned.m8n8.x4.shared.b16 {%0,%1,%2,%3}, [%4];"
        : "=r"(r[0]), "=r"(r[1]), "=r"(r[2]), "=r"(r[3]) : "r"(addr));
}

// ---------------------------------------------------------------------------
// K2: FUSED agg + gemm. Block = 128 rows.
// Phase 1 (agg, R13 inner loop): 8 warps x 16 rows; y written straight into
// the gemm A-tile in smem (Ysm, stride 272B -> conflict-free stores + LDSM),
// beta into smem. No y global round-trip.
// Phase 2 (gemm): A full-width resident in Ysm; W staged in 4 x 32-col
// phases; proven HMMA fragment math; out[r] = y[r] @ W^T + beta[r]*b.
// Static smem 47.6 KB (< 48 KB default).
// ---------------------------------------------------------------------------
__global__ void __launch_bounds__(256)
fused_kernel(const float* __restrict__ bvec, float* __restrict__ out, int n) {
    __shared__ __half Ysm[TILE_M * YPAD];          // 34816 B
    __shared__ __half Wsm[DIM * WPAD];             // 10240 B
    __shared__ float  Bsm[TILE_M];                 //   512 B
    __shared__ unsigned long long pairs[8][32];    //  2048 B

    int tid  = threadIdx.x;
    int wid  = tid >> 5;
    int lane = tid & 31;
    int row0 = blockIdx.x * TILE_M;
    int half = lane >> 4;
    int li   = lane & 15;

    // ============ Phase 1: aggregation into Ysm ============
    for (int r8 = 0; r8 < 16; r8++) {
        int lrow = wid * 16 + r8;
        int row  = row0 + lrow;

        if (row < n) {
            int degr = g_deg[row];
            int degc = min(degr, MAXDEG);

            float acc[8];
#pragma unroll
            for (int t = 0; t < 8; t++) acc[t] = 0.f;
            float s = 0.f;

            for (int base = 0; base < degc; base += 32) {
                int m = min(32, degc - base);
                {
                    unsigned long long pk = 0ull;
                    if (lane < m) {
                        int   c  = g_bucket[(size_t)row * MAXDEG + base + lane];
                        float dc = rsqrtf((float)max(g_deg[c], 1));
                        pk = ((unsigned long long)__float_as_uint(dc) << 32) |
                             (unsigned int)c;
                    }
                    pairs[wid][lane] = pk;
                }
                __syncwarp();

#pragma unroll 8
                for (int j = 0; j < m; j += 2) {
                    unsigned long long pk = pairs[wid][j + half];
                    int   cj  = (int)(unsigned int)pk;
                    float dcj = __uint_as_float((unsigned int)(pk >> 32));
                    uint4 v = *(const uint4*)(g_xh + (size_t)cj * DIM + li * 8);
                    const __half2* hp = (const __half2*)&v;
#pragma unroll
                    for (int t = 0; t < 4; t++) {
                        float2 f = __half22float2(hp[t]);
                        acc[t * 2 + 0] += dcj * f.x;
                        acc[t * 2 + 1] += dcj * f.y;
                    }
                    s += dcj;
                }
                __syncwarp();
            }

#pragma unroll
            for (int t = 0; t < 8; t++)
                acc[t] += __shfl_down_sync(0xffffffffu, acc[t], 16);
            s += __shfl_down_sync(0xffffffffu, s, 16);

            float dr = rsqrtf((float)max(degr, 1));
            float d2 = dr * dr;

            if (lane < 16) {
                uint4 xv = *(const uint4*)(g_xh + (size_t)row * DIM + li * 8);
                const __half2* xp = (const __half2*)&xv;
                uint4 yo;
                uint32_t* yw = (uint32_t*)&yo;
#pragma unroll
                for (int t = 0; t < 4; t++) {
                    float2 xf = __half22float2(xp[t]);
                    __half2 p = __float22half2_rn(
                        make_float2(dr * acc[t * 2 + 0] + d2 * xf.x,
                                    dr * acc[t * 2 + 1] + d2 * xf.y));
                    yw[t] = *(const uint32_t*)&p;
                }
                *(uint4*)&Ysm[lrow * YPAD + li * 8] = yo;
            }
            if (lane == 0) Bsm[lrow] = dr * s + d2;
        } else {
            if (lane < 16)
                *(uint4*)&Ysm[lrow * YPAD + li * 8] = make_uint4(0, 0, 0, 0);
            if (lane == 0) Bsm[lrow] = 0.f;
        }
    }
    __syncthreads();

    // ============ Phase 2: HMMA GEMM ============
    int warpM = wid & 3;
    int warpN = wid >> 2;
    int g     = lane >> 2;
    int i2    = (lane & 3) * 2;

    int grp = lane >> 3;
    int lr  = lane & 7;
    int ro  = (grp & 1) * 8 + lr;
    int co  = (grp >> 1) * 8;

    uint32_t ybase = smem_u32(Ysm);
    uint32_t wbase = smem_u32(Wsm);

    float c[2][8][4];
#pragma unroll
    for (int mt = 0; mt < 2; mt++)
#pragma unroll
        for (int nt = 0; nt < 8; nt++)
#pragma unroll
            for (int q = 0; q < 4; q++) c[mt][nt][q] = 0.f;

#pragma unroll
    for (int p = 0; p < 4; p++) {
        int kb0 = p * 32;
        __syncthreads();
        // Stage W[.][kb0..kb0+32): 512 x 16B chunks, 2 per thread
#pragma unroll
        for (int it = 0; it < 2; it++) {
            int idx = tid + it * 256;
            int row = idx >> 2;
            int ch  = (idx & 3) * 8;
            *(uint4*)&Wsm[row * WPAD + ch] =
                *(const uint4*)(g_Wh + row * DIM + kb0 + ch);
        }
        __syncthreads();

#pragma unroll
        for (int k = 0; k < 2; k++) {
            int kcW = k * 16 + co;
            int kcA = kb0 + kcW;

            uint32_t a[2][4];
#pragma unroll
            for (int mt = 0; mt < 2; mt++) {
                uint32_t addr = ybase +
                    ((warpM * 32 + mt * 16 + ro) * YPAD + kcA) * 2;
                ldsm_x4(a[mt], addr);
            }

#pragma unroll
            for (int ntp = 0; ntp < 4; ntp++) {
                uint32_t bfr[4];
                uint32_t addr = wbase +
                    ((warpN * 64 + ntp * 16 + ro) * WPAD + kcW) * 2;
                ldsm_x4(bfr, addr);
#pragma unroll
                for (int mt = 0; mt < 2; mt++) {
                    mma16816(c[mt][ntp * 2 + 0], a[mt][0], a[mt][1], a[mt][2], a[mt][3],
                             bfr[0], bfr[2]);
                    mma16816(c[mt][ntp * 2 + 1], a[mt][0], a[mt][1], a[mt][2], a[mt][3],
                             bfr[1], bfr[3]);
                }
            }
        }
    }

    int n0 = warpN * 64;
#pragma unroll
    for (int mt = 0; mt < 2; mt++) {
        int l0 = warpM * 32 + mt * 16 + g;
        int r0 = row0 + l0;
        int r1 = r0 + 8;
        float be0 = Bsm[l0];
        float be1 = Bsm[l0 + 8];
#pragma unroll
        for (int nt = 0; nt < 8; nt++) {
            int col = n0 + nt * 8 + i2;
            float2 bv = *(const float2*)(bvec + col);
            if (r0 < n) {
                *(float2*)(out + (size_t)r0 * DIM + col) =
                    make_float2(c[mt][nt][0] + be0 * bv.x,
                                c[mt][nt][1] + be0 * bv.y);
            }
            if (r1 < n) {
                *(float2*)(out + (size_t)r1 * DIM + col) =
                    make_float2(c[mt][nt][2] + be1 * bv.x,
                                c[mt][nt][3] + be1 * bv.y);
            }
        }
    }
}

// ---------------------------------------------------------------------------
// Launch (3 kernels: init -> fill -> fused)
// ---------------------------------------------------------------------------
extern "C" void kernel_launch(void* const* d_in, const int* in_sizes, int n_in,
                              void* d_out, int out_size) {
    const float* x   = (const float*)d_in[0];
    const int*   ei  = (const int*)d_in[1];
    const float* W   = (const float*)d_in[2];
    const float* b   = (const float*)d_in[3];
    float*       out = (float*)d_out;

    int n = in_sizes[0] / DIM;
    int e = in_sizes[1] / 2;

    size_t init_tot = (size_t)n * (DIM / 8);   // threads (8 floats each)
    init_kernel<<<(int)((init_tot + 255) / 256), 256>>>(x, W, n);
    fill_kernel<<<(e + 255) / 256, 256>>>(ei, e, n);
    fused_kernel<<<(n + TILE_M - 1) / TILE_M, 256>>>(b, out, n);
}

// round 15
// speedup vs baseline: 1.5070x; 1.5070x over previous
#include <cuda_runtime.h>
#include <cuda_fp16.h>
#include <cstdint>

#define DIM     128
#define NMAX    100000
#define MAXDEG  128
#define TILE_M  128
#define SPAD    72          // smem row stride in halfs (64 data + 8 pad = 144B)

// ---------------------------------------------------------------------------
// Scratch (allocation-free rule: module-scope device arrays)
// ---------------------------------------------------------------------------
__device__ int    g_deg[NMAX];
__device__ int    g_bucket[(size_t)NMAX * MAXDEG];     // 51.2 MB
__device__ __half g_xh[(size_t)NMAX * DIM];            // 25.6 MB  x in fp16
__device__ __half g_yh[(size_t)(NMAX + TILE_M) * DIM]; // fp16 y (zero pad tail)
__device__ __half g_Wh[DIM * DIM];                     // W in fp16
__device__ float  g_beta[NMAX];

__device__ __forceinline__ uint32_t smem_u32(const void* p) {
    uint32_t a;
    asm("{ .reg .u64 t; cvta.to.shared.u64 t, %1; cvt.u32.u64 %0, t; }"
        : "=r"(a) : "l"(p));
    return a;
}

__device__ __forceinline__ uint4 cvt8_f32_to_h16(float4 v0, float4 v1) {
    uint4 o;
    __half2 h;
    h = __float22half2_rn(make_float2(v0.x, v0.y)); o.x = *(const uint32_t*)&h;
    h = __float22half2_rn(make_float2(v0.z, v0.w)); o.y = *(const uint32_t*)&h;
    h = __float22half2_rn(make_float2(v1.x, v1.y)); o.z = *(const uint32_t*)&h;
    h = __float22half2_rn(make_float2(v1.z, v1.w)); o.w = *(const uint32_t*)&h;
    return o;
}

// ---------------------------------------------------------------------------
// K0: init — zero degrees + x->fp16 + W->fp16 (8 floats/thread, proven R9/R13)
// ---------------------------------------------------------------------------
__global__ void init_kernel(const float* __restrict__ x,
                            const float* __restrict__ W, int n) {
    int i = blockIdx.x * blockDim.x + threadIdx.x;       // one per 8 floats
    size_t total8 = (size_t)n * (DIM / 8);               // 1.6M
    if ((size_t)i < total8) {
        const float4* p = (const float4*)x + (size_t)i * 2;
        ((uint4*)g_xh)[i] = cvt8_f32_to_h16(p[0], p[1]);
    }
    if (i < n) g_deg[i] = 0;
    if (i < DIM * DIM / 8) {
        const float4* p = (const float4*)W + (size_t)i * 2;
        ((uint4*)g_Wh)[i] = cvt8_f32_to_h16(p[0], p[1]);
    }
}

// ---------------------------------------------------------------------------
// K1: count degrees + scatter neighbor lists. 2 edges/thread (int2 loads).
// ---------------------------------------------------------------------------
__global__ void fill_kernel(const int* __restrict__ ei, int e, int n) {
    int i = blockIdx.x * blockDim.x + threadIdx.x;       // one per 2 edges
    int e2 = e >> 1;
    if (i < e2) {
        int2 row2 = *(const int2*)(ei + 2 * i);
        int2 col2 = *(const int2*)(ei + (size_t)e + 2 * i);
#pragma unroll
        for (int q = 0; q < 2; q++) {
            int row = q ? row2.y : row2.x;
            int col = q ? col2.y : col2.x;
            if ((unsigned)row < (unsigned)n && (unsigned)col < (unsigned)n) {
                int slot = atomicAdd(&g_deg[row], 1);
                if (slot < MAXDEG) g_bucket[(size_t)row * MAXDEG + slot] = col;
            }
        }
    }
    // odd tail (e is even in this problem, but stay safe)
    if (i == 0 && (e & 1)) {
        int row = ei[e - 1];
        int col = ei[(size_t)e + e - 1];
        if ((unsigned)row < (unsigned)n && (unsigned)col < (unsigned)n) {
            int slot = atomicAdd(&g_deg[row], 1);
            if (slot < MAXDEG) g_bucket[(size_t)row * MAXDEG + slot] = col;
        }
    }
}

// ---------------------------------------------------------------------------
// K2: warp-per-row aggregation (R13 smem-pairs version; deg>=1 guaranteed)
// y[r] = d_r * sum_c d_c * x[c] + d_r^2 * x[r];  beta[r] = d_r*sum d_c + d_r^2
// ---------------------------------------------------------------------------
__global__ void __launch_bounds__(256)
agg_kernel(int n) {
    __shared__ unsigned long long pairs[8][32];   // per-warp (dc<<32 | c)

    int warp = threadIdx.x >> 5;                  // warp within block
    int gw   = (blockIdx.x * blockDim.x + threadIdx.x) >> 5;
    int lane = threadIdx.x & 31;
    if (gw >= n) return;

    int degr = g_deg[gw];
    int degc = min(degr, MAXDEG);
    int half = lane >> 4;
    int li   = lane & 15;

    float acc[8];
#pragma unroll
    for (int t = 0; t < 8; t++) acc[t] = 0.f;
    float s = 0.f;

    for (int base = 0; base < degc; base += 32) {
        int m = min(32, degc - base);
        {
            unsigned long long pk = 0ull;         // c=0, dc=0 for lanes >= m
            if (lane < m) {
                int   c  = g_bucket[(size_t)gw * MAXDEG + base + lane];
                float dc = rsqrtf((float)g_deg[c]);   // deg >= 1 guaranteed
                pk = ((unsigned long long)__float_as_uint(dc) << 32) |
                     (unsigned int)c;
            }
            pairs[warp][lane] = pk;
        }
        __syncwarp();

#pragma unroll 8
        for (int j = 0; j < m; j += 2) {
            unsigned long long pk = pairs[warp][j + half];
            int   cj  = (int)(unsigned int)pk;
            float dcj = __uint_as_float((unsigned int)(pk >> 32));
            uint4 v = *(const uint4*)(g_xh + (size_t)cj * DIM + li * 8);
            const __half2* hp = (const __half2*)&v;
#pragma unroll
            for (int t = 0; t < 4; t++) {
                float2 f = __half22float2(hp[t]);
                acc[t * 2 + 0] += dcj * f.x;
                acc[t * 2 + 1] += dcj * f.y;
            }
            s += dcj;
        }
        __syncwarp();
    }

#pragma unroll
    for (int t = 0; t < 8; t++)
        acc[t] += __shfl_down_sync(0xffffffffu, acc[t], 16);
    s += __shfl_down_sync(0xffffffffu, s, 16);

    float dr = rsqrtf((float)degr);               // deg >= 1 guaranteed
    float d2 = dr * dr;

    if (lane < 16) {
        uint4 xv = *(const uint4*)(g_xh + (size_t)gw * DIM + li * 8);
        const __half2* xp = (const __half2*)&xv;
        uint4 yo;
        uint32_t* yw = (uint32_t*)&yo;
#pragma unroll
        for (int t = 0; t < 4; t++) {
            float2 xf = __half22float2(xp[t]);
            __half2 p = __float22half2_rn(
                make_float2(dr * acc[t * 2 + 0] + d2 * xf.x,
                            dr * acc[t * 2 + 1] + d2 * xf.y));
            yw[t] = *(const uint32_t*)&p;
        }
        *(uint4*)(g_yh + (size_t)gw * DIM + li * 8) = yo;
    }
    if (lane == 0) g_beta[gw] = dr * s + d2;
}

// ---------------------------------------------------------------------------
// mma.sync m16n8k16 fp16 -> fp32
// ---------------------------------------------------------------------------
__device__ __forceinline__ void mma16816(float c[4],
                                         uint32_t a0, uint32_t a1,
                                         uint32_t a2, uint32_t a3,
                                         uint32_t b0, uint32_t b1) {
    asm volatile(
        "mma.sync.aligned.m16n8k16.row.col.f32.f16.f16.f32 "
        "{%0,%1,%2,%3}, {%4,%5,%6,%7}, {%8,%9}, {%0,%1,%2,%3};"
        : "+f"(c[0]), "+f"(c[1]), "+f"(c[2]), "+f"(c[3])
        : "r"(a0), "r"(a1), "r"(a2), "r"(a3), "r"(b0), "r"(b1));
}

__device__ __forceinline__ void ldsm_x4(uint32_t r[4], uint32_t addr) {
    asm volatile(
        "ldmatrix.sync.aligned.m8n8.x4.shared.b16 {%0,%1,%2,%3}, [%4];"
        : "=r"(r[0]), "=r"(r[1]), "=r"(r[2]), "=r"(r[3]) : "r"(addr));
}

// ---------------------------------------------------------------------------
// K3: HMMA GEMM via smem + ldmatrix — EXACT R13 version (proven 24.2us)
// ---------------------------------------------------------------------------
__global__ void __launch_bounds__(256)
gemm_mma_kernel(const float* __restrict__ bvec, float* __restrict__ out, int n) {
    __shared__ __half Wsm[DIM * SPAD];   // 18432 B
    __shared__ __half Ysm[DIM * SPAD];   // 18432 B

    int tid   = threadIdx.x;
    int wid   = tid >> 5;
    int lane  = tid & 31;
    int warpM = wid & 3;
    int warpN = wid >> 2;
    int row0  = blockIdx.x * TILE_M;
    int g     = lane >> 2;
    int i2    = (lane & 3) * 2;

    int grp = lane >> 3;
    int lr  = lane & 7;
    int ro  = (grp & 1) * 8 + lr;
    int co  = (grp >> 1) * 8;

    uint32_t ybase = smem_u32(Ysm);
    uint32_t wbase = smem_u32(Wsm);

    float c[2][8][4];
#pragma unroll
    for (int mt = 0; mt < 2; mt++)
#pragma unroll
        for (int nt = 0; nt < 8; nt++)
#pragma unroll
            for (int q = 0; q < 4; q++) c[mt][nt][q] = 0.f;

#pragma unroll
    for (int p = 0; p < 2; p++) {
        int kb0 = p * 64;
        __syncthreads();
#pragma unroll
        for (int it = 0; it < 4; it++) {
            int idx = tid + it * 256;
            int row = idx >> 3;
            int ch  = (idx & 7) * 8;
            *(uint4*)&Wsm[row * SPAD + ch] =
                *(const uint4*)(g_Wh + row * DIM + kb0 + ch);
            *(uint4*)&Ysm[row * SPAD + ch] =
                *(const uint4*)(g_yh + (size_t)(row0 + row) * DIM + kb0 + ch);
        }
        __syncthreads();

#pragma unroll
        for (int k = 0; k < 4; k++) {
            int kc = k * 16 + co;

            uint32_t a[2][4];
#pragma unroll
            for (int mt = 0; mt < 2; mt++) {
                uint32_t addr = ybase +
                    ((warpM * 32 + mt * 16 + ro) * SPAD + kc) * 2;
                ldsm_x4(a[mt], addr);
            }

#pragma unroll
            for (int ntp = 0; ntp < 4; ntp++) {
                uint32_t bfr[4];
                uint32_t addr = wbase +
                    ((warpN * 64 + ntp * 16 + ro) * SPAD + kc) * 2;
                ldsm_x4(bfr, addr);
#pragma unroll
                for (int mt = 0; mt < 2; mt++) {
                    mma16816(c[mt][ntp * 2 + 0], a[mt][0], a[mt][1], a[mt][2], a[mt][3],
                             bfr[0], bfr[2]);
                    mma16816(c[mt][ntp * 2 + 1], a[mt][0], a[mt][1], a[mt][2], a[mt][3],
                             bfr[1], bfr[3]);
                }
            }
        }
    }

    int n0 = warpN * 64;
#pragma unroll
    for (int mt = 0; mt < 2; mt++) {
        int r0 = row0 + warpM * 32 + mt * 16 + g;
        int r1 = r0 + 8;
        float be0 = (r0 < n) ? g_beta[r0] : 0.f;
        float be1 = (r1 < n) ? g_beta[r1] : 0.f;
#pragma unroll
        for (int nt = 0; nt < 8; nt++) {
            int col = n0 + nt * 8 + i2;
            float2 bv = *(const float2*)(bvec + col);
            if (r0 < n) {
                *(float2*)(out + (size_t)r0 * DIM + col) =
                    make_float2(c[mt][nt][0] + be0 * bv.x,
                                c[mt][nt][1] + be0 * bv.y);
            }
            if (r1 < n) {
                *(float2*)(out + (size_t)r1 * DIM + col) =
                    make_float2(c[mt][nt][2] + be1 * bv.x,
                                c[mt][nt][3] + be1 * bv.y);
            }
        }
    }
}

// ---------------------------------------------------------------------------
// Launch (R13 structure: init -> fill -> agg -> gemm)
// ---------------------------------------------------------------------------
extern "C" void kernel_launch(void* const* d_in, const int* in_sizes, int n_in,
                              void* d_out, int out_size) {
    const float* x   = (const float*)d_in[0];
    const int*   ei  = (const int*)d_in[1];
    const float* W   = (const float*)d_in[2];
    const float* b   = (const float*)d_in[3];
    float*       out = (float*)d_out;

    int n = in_sizes[0] / DIM;
    int e = in_sizes[1] / 2;

    size_t init_tot = (size_t)n * (DIM / 8);   // threads (8 floats each)
    init_kernel<<<(int)((init_tot + 255) / 256), 256>>>(x, W, n);
    fill_kernel<<<((e / 2) + 255) / 256, 256>>>(ei, e, n);
    agg_kernel<<<((n * 32) + 255) / 256, 256>>>(n);
    gemm_mma_kernel<<<(n + TILE_M - 1) / TILE_M, 256>>>(b, out, n);
}

// round 16
// speedup vs baseline: 1.5119x; 1.0032x over previous
#include <cuda_runtime.h>
#include <cuda_fp16.h>
#include <cstdint>

#define DIM     128
#define NMAX    100000
#define MAXDEG  128
#define TILE_M  128
#define YPAD    136         // smem row stride in halfs (272B; LDSM conflict-free, proven R14)
#define GSMEM   (2 * TILE_M * YPAD * (int)sizeof(__half))   // 69632 B

// ---------------------------------------------------------------------------
// Scratch (allocation-free rule: module-scope device arrays)
// ---------------------------------------------------------------------------
__device__ int    g_deg[NMAX];
__device__ int    g_bucket[(size_t)NMAX * MAXDEG];     // 51.2 MB
__device__ __half g_xh[(size_t)NMAX * DIM];            // 25.6 MB  x in fp16
__device__ __half g_yh[(size_t)(NMAX + TILE_M) * DIM]; // fp16 y (zero pad tail)
__device__ __half g_Wh[DIM * DIM];                     // W in fp16
__device__ float  g_beta[NMAX];

__device__ __forceinline__ uint32_t smem_u32(const void* p) {
    uint32_t a;
    asm("{ .reg .u64 t; cvta.to.shared.u64 t, %1; cvt.u32.u64 %0, t; }"
        : "=r"(a) : "l"(p));
    return a;
}

__device__ __forceinline__ uint4 cvt8_f32_to_h16(float4 v0, float4 v1) {
    uint4 o;
    __half2 h;
    h = __float22half2_rn(make_float2(v0.x, v0.y)); o.x = *(const uint32_t*)&h;
    h = __float22half2_rn(make_float2(v0.z, v0.w)); o.y = *(const uint32_t*)&h;
    h = __float22half2_rn(make_float2(v1.x, v1.y)); o.z = *(const uint32_t*)&h;
    h = __float22half2_rn(make_float2(v1.z, v1.w)); o.w = *(const uint32_t*)&h;
    return o;
}

// ---------------------------------------------------------------------------
// K0: init — zero degrees + x->fp16 + W->fp16 (8 floats/thread, proven)
// ---------------------------------------------------------------------------
__global__ void init_kernel(const float* __restrict__ x,
                            const float* __restrict__ W, int n) {
    int i = blockIdx.x * blockDim.x + threadIdx.x;       // one per 8 floats
    size_t total8 = (size_t)n * (DIM / 8);               // 1.6M
    if ((size_t)i < total8) {
        const float4* p = (const float4*)x + (size_t)i * 2;
        ((uint4*)g_xh)[i] = cvt8_f32_to_h16(p[0], p[1]);
    }
    if (i < n) g_deg[i] = 0;
    if (i < DIM * DIM / 8) {
        const float4* p = (const float4*)W + (size_t)i * 2;
        ((uint4*)g_Wh)[i] = cvt8_f32_to_h16(p[0], p[1]);
    }
}

// ---------------------------------------------------------------------------
// K1: count degrees + scatter neighbor lists. 2 edges/thread (proven R15).
// ---------------------------------------------------------------------------
__global__ void fill_kernel(const int* __restrict__ ei, int e, int n) {
    int i = blockIdx.x * blockDim.x + threadIdx.x;       // one per 2 edges
    int e2 = e >> 1;
    if (i < e2) {
        int2 row2 = *(const int2*)(ei + 2 * i);
        int2 col2 = *(const int2*)(ei + (size_t)e + 2 * i);
#pragma unroll
        for (int q = 0; q < 2; q++) {
            int row = q ? row2.y : row2.x;
            int col = q ? col2.y : col2.x;
            if ((unsigned)row < (unsigned)n && (unsigned)col < (unsigned)n) {
                int slot = atomicAdd(&g_deg[row], 1);
                if (slot < MAXDEG) g_bucket[(size_t)row * MAXDEG + slot] = col;
            }
        }
    }
    if (i == 0 && (e & 1)) {
        int row = ei[e - 1];
        int col = ei[(size_t)e + e - 1];
        if ((unsigned)row < (unsigned)n && (unsigned)col < (unsigned)n) {
            int slot = atomicAdd(&g_deg[row], 1);
            if (slot < MAXDEG) g_bucket[(size_t)row * MAXDEG + slot] = col;
        }
    }
}

// ---------------------------------------------------------------------------
// K2: warp-per-row aggregation (proven R13/R15; at the LTS roofline)
// y[r] = d_r * sum_c d_c * x[c] + d_r^2 * x[r];  beta[r] = d_r*sum d_c + d_r^2
// ---------------------------------------------------------------------------
__global__ void __launch_bounds__(256)
agg_kernel(int n) {
    __shared__ unsigned long long pairs[8][32];   // per-warp (dc<<32 | c)

    int warp = threadIdx.x >> 5;
    int gw   = (blockIdx.x * blockDim.x + threadIdx.x) >> 5;
    int lane = threadIdx.x & 31;
    if (gw >= n) return;

    int degr = g_deg[gw];
    int degc = min(degr, MAXDEG);
    int half = lane >> 4;
    int li   = lane & 15;

    float acc[8];
#pragma unroll
    for (int t = 0; t < 8; t++) acc[t] = 0.f;
    float s = 0.f;

    for (int base = 0; base < degc; base += 32) {
        int m = min(32, degc - base);
        {
            unsigned long long pk = 0ull;
            if (lane < m) {
                int   c  = g_bucket[(size_t)gw * MAXDEG + base + lane];
                float dc = rsqrtf((float)g_deg[c]);   // deg >= 1 guaranteed
                pk = ((unsigned long long)__float_as_uint(dc) << 32) |
                     (unsigned int)c;
            }
            pairs[warp][lane] = pk;
        }
        __syncwarp();

#pragma unroll 8
        for (int j = 0; j < m; j += 2) {
            unsigned long long pk = pairs[warp][j + half];
            int   cj  = (int)(unsigned int)pk;
            float dcj = __uint_as_float((unsigned int)(pk >> 32));
            uint4 v = *(const uint4*)(g_xh + (size_t)cj * DIM + li * 8);
            const __half2* hp = (const __half2*)&v;
#pragma unroll
            for (int t = 0; t < 4; t++) {
                float2 f = __half22float2(hp[t]);
                acc[t * 2 + 0] += dcj * f.x;
                acc[t * 2 + 1] += dcj * f.y;
            }
            s += dcj;
        }
        __syncwarp();
    }

#pragma unroll
    for (int t = 0; t < 8; t++)
        acc[t] += __shfl_down_sync(0xffffffffu, acc[t], 16);
    s += __shfl_down_sync(0xffffffffu, s, 16);

    float dr = rsqrtf((float)degr);
    float d2 = dr * dr;

    if (lane < 16) {
        uint4 xv = *(const uint4*)(g_xh + (size_t)gw * DIM + li * 8);
        const __half2* xp = (const __half2*)&xv;
        uint4 yo;
        uint32_t* yw = (uint32_t*)&yo;
#pragma unroll
        for (int t = 0; t < 4; t++) {
            float2 xf = __half22float2(xp[t]);
            __half2 p = __float22half2_rn(
                make_float2(dr * acc[t * 2 + 0] + d2 * xf.x,
                            dr * acc[t * 2 + 1] + d2 * xf.y));
            yw[t] = *(const uint32_t*)&p;
        }
        *(uint4*)(g_yh + (size_t)gw * DIM + li * 8) = yo;
    }
    if (lane == 0) g_beta[gw] = dr * s + d2;
}

// ---------------------------------------------------------------------------
// mma.sync m16n8k16 fp16 -> fp32
// ---------------------------------------------------------------------------
__device__ __forceinline__ void mma16816(float c[4],
                                         uint32_t a0, uint32_t a1,
                                         uint32_t a2, uint32_t a3,
                                         uint32_t b0, uint32_t b1) {
    asm volatile(
        "mma.sync.aligned.m16n8k16.row.col.f32.f16.f16.f32 "
        "{%0,%1,%2,%3}, {%4,%5,%6,%7}, {%8,%9}, {%0,%1,%2,%3};"
        : "+f"(c[0]), "+f"(c[1]), "+f"(c[2]), "+f"(c[3])
        : "r"(a0), "r"(a1), "r"(a2), "r"(a3), "r"(b0), "r"(b1));
}

__device__ __forceinline__ void ldsm_x4(uint32_t r[4], uint32_t addr) {
    asm volatile(
        "ldmatrix.sync.aligned.m8n8.x4.shared.b16 {%0,%1,%2,%3}, [%4];"
        : "=r"(r[0]), "=r"(r[1]), "=r"(r[2]), "=r"(r[3]) : "r"(addr));
}

// ---------------------------------------------------------------------------
// K3: HMMA GEMM, SINGLE PHASE: full-K Y and W tiles resident in dynamic smem
// (69.6 KB). One staging burst (16 uint4/thread, MLP 16), ONE sync, then 8
// uninterrupted k-steps. Fragment math identical to R13/R15.
// ---------------------------------------------------------------------------
__global__ void __launch_bounds__(256)
gemm_mma_kernel(const float* __restrict__ bvec, float* __restrict__ out, int n) {
    extern __shared__ __half dsm[];
    __half* Ysm = dsm;                       // [128][136]
    __half* Wsm = dsm + TILE_M * YPAD;       // [128][136]

    int tid   = threadIdx.x;
    int wid   = tid >> 5;
    int lane  = tid & 31;
    int warpM = wid & 3;
    int warpN = wid >> 2;
    int row0  = blockIdx.x * TILE_M;
    int g     = lane >> 2;
    int i2    = (lane & 3) * 2;

    int grp = lane >> 3;
    int lr  = lane & 7;
    int ro  = (grp & 1) * 8 + lr;
    int co  = (grp >> 1) * 8;

    // --- Single staging burst: 2048 uint4 chunks per tile, 8 per thread ---
#pragma unroll
    for (int it = 0; it < 8; it++) {
        int idx = tid + it * 256;            // 0..2047
        int row = idx >> 4;                  // 16 chunks per 128-half row
        int ch  = (idx & 15) * 8;
        *(uint4*)&Wsm[row * YPAD + ch] =
            *(const uint4*)(g_Wh + row * DIM + ch);
        *(uint4*)&Ysm[row * YPAD + ch] =
            *(const uint4*)(g_yh + (size_t)(row0 + row) * DIM + ch);
    }
    __syncthreads();

    uint32_t ybase = smem_u32(Ysm);
    uint32_t wbase = smem_u32(Wsm);

    float c[2][8][4];
#pragma unroll
    for (int mt = 0; mt < 2; mt++)
#pragma unroll
        for (int nt = 0; nt < 8; nt++)
#pragma unroll
            for (int q = 0; q < 4; q++) c[mt][nt][q] = 0.f;

#pragma unroll
    for (int k = 0; k < 8; k++) {
        int kc = k * 16 + co;

        uint32_t a[2][4];
#pragma unroll
        for (int mt = 0; mt < 2; mt++) {
            uint32_t addr = ybase +
                ((warpM * 32 + mt * 16 + ro) * YPAD + kc) * 2;
            ldsm_x4(a[mt], addr);
        }

#pragma unroll
        for (int ntp = 0; ntp < 4; ntp++) {
            uint32_t bfr[4];
            uint32_t addr = wbase +
                ((warpN * 64 + ntp * 16 + ro) * YPAD + kc) * 2;
            ldsm_x4(bfr, addr);
#pragma unroll
            for (int mt = 0; mt < 2; mt++) {
                mma16816(c[mt][ntp * 2 + 0], a[mt][0], a[mt][1], a[mt][2], a[mt][3],
                         bfr[0], bfr[2]);
                mma16816(c[mt][ntp * 2 + 1], a[mt][0], a[mt][1], a[mt][2], a[mt][3],
                         bfr[1], bfr[3]);
            }
        }
    }

    int n0 = warpN * 64;
#pragma unroll
    for (int mt = 0; mt < 2; mt++) {
        int r0 = row0 + warpM * 32 + mt * 16 + g;
        int r1 = r0 + 8;
        float be0 = (r0 < n) ? g_beta[r0] : 0.f;
        float be1 = (r1 < n) ? g_beta[r1] : 0.f;
#pragma unroll
        for (int nt = 0; nt < 8; nt++) {
            int col = n0 + nt * 8 + i2;
            float2 bv = *(const float2*)(bvec + col);
            if (r0 < n) {
                *(float2*)(out + (size_t)r0 * DIM + col) =
                    make_float2(c[mt][nt][0] + be0 * bv.x,
                                c[mt][nt][1] + be0 * bv.y);
            }
            if (r1 < n) {
                *(float2*)(out + (size_t)r1 * DIM + col) =
                    make_float2(c[mt][nt][2] + be1 * bv.x,
                                c[mt][nt][3] + be1 * bv.y);
            }
        }
    }
}

// ---------------------------------------------------------------------------
// Launch (init -> fill -> agg -> gemm)
// ---------------------------------------------------------------------------
extern "C" void kernel_launch(void* const* d_in, const int* in_sizes, int n_in,
                              void* d_out, int out_size) {
    const float* x   = (const float*)d_in[0];
    const int*   ei  = (const int*)d_in[1];
    const float* W   = (const float*)d_in[2];
    const float* b   = (const float*)d_in[3];
    float*       out = (float*)d_out;

    int n = in_sizes[0] / DIM;
    int e = in_sizes[1] / 2;

    cudaFuncSetAttribute(gemm_mma_kernel,
                         cudaFuncAttributeMaxDynamicSharedMemorySize, GSMEM);

    size_t init_tot = (size_t)n * (DIM / 8);   // threads (8 floats each)
    init_kernel<<<(int)((init_tot + 255) / 256), 256>>>(x, W, n);
    fill_kernel<<<((e / 2) + 255) / 256, 256>>>(ei, e, n);
    agg_kernel<<<((n * 32) + 255) / 256, 256>>>(n);
    gemm_mma_kernel<<<(n + TILE_M - 1) / TILE_M, 256, GSMEM>>>(b, out, n);
}